// round 10
// baseline (speedup 1.0000x reference)
#include <cuda_runtime.h>

#define BATCH 8
#define HH 1024
#define WW 1024

#define TILE 104          // valid output span per tile dim
#define HALO 12           // >= 10 needed; 12 keeps float4 alignment
#define EXT  128          // TILE + 2*HALO
#define NWARP 16
#define RPW  8            // rows per warp (NWARP*RPW == EXT)
#define NT   512
#define NITER 10

#define SMEM_BYTES ((2*EXT*EXT + 2*NWARP*EXT) * 4)

typedef unsigned long long ull;

// ---- packed f32x2 helpers (sm_100+; 2x flops per instruction) ----
__device__ __forceinline__ ull pk2(float lo, float hi) {
    ull r; asm("mov.b64 %0, {%1, %2};" : "=l"(r) : "f"(lo), "f"(hi)); return r;
}
__device__ __forceinline__ void upk2(ull v, float& lo, float& hi) {
    asm("mov.b64 {%0, %1}, %2;" : "=f"(lo), "=f"(hi) : "l"(v));
}
__device__ __forceinline__ ull fma2(ull a, ull b, ull c) {
    ull r; asm("fma.rn.f32x2 %0, %1, %2, %3;" : "=l"(r) : "l"(a), "l"(b), "l"(c)); return r;
}
__device__ __forceinline__ ull add2(ull a, ull b) {
    ull r; asm("add.rn.f32x2 %0, %1, %2;" : "=l"(r) : "l"(a), "l"(b)); return r;
}
__device__ __forceinline__ ull mul2(ull a, ull b) {
    ull r; asm("mul.rn.f32x2 %0, %1, %2;" : "=l"(r) : "l"(a), "l"(b)); return r;
}

// sigmoid(2x) = 0.5*tanh(x) + 0.5  -> one MUFU
__device__ __forceinline__ float tanh_fast(float x) {
    float y;
    asm("tanh.approx.f32 %0, %1;" : "=f"(y) : "f"(x));
    return y;
}

template <bool INTERIOR>
__device__ __forceinline__ void run_tile(
    const float* __restrict__ o, const float* __restrict__ vf,
    float* __restrict__ out, float* sm, int tx, int ty, int b)
{
    float* sv0 = sm;                    // vf0 [EXT][EXT] (zeroed outside image)
    float* sv1 = sm + EXT * EXT;        // vf1 [EXT][EXT]
    float* xu  = sm + 2 * EXT * EXT;    // per-warp u row-0 exchange [NWARP][EXT]
    float* xq  = xu + NWARP * EXT;      // per-warp q row-7 exchange [NWARP][EXT]

    const int tid  = threadIdx.x;
    const int w    = tid >> 5;
    const int lane = tid & 31;
    const int gi0 = ty * TILE - HALO;
    const int gj0 = tx * TILE - HALO;            // multiple of 4
    const int colbase = gj0 + lane * 4;          // global col of this lane's elem 0
    const int cb = INTERIOR ? colbase : min(max(colbase, 0), WW - 4); // 16B aligned
    const int er0 = w * RPW;
    const float* ob = o + (size_t)b * HH * WW;

    const ull M1 = pk2(-1.f, -1.f);
    const ull MH = pk2(-0.5f, -0.5f);
    const ull HF = pk2(0.5f, 0.5f);

    // column in-image mask (boundary tiles only)
    float cmx, cmy, cmz, cmw;
    if (!INTERIOR) {
        cmx = ((unsigned)(colbase + 0) < WW) ? 1.f : 0.f;
        cmy = ((unsigned)(colbase + 1) < WW) ? 1.f : 0.f;
        cmz = ((unsigned)(colbase + 2) < WW) ? 1.f : 0.f;
        cmw = ((unsigned)(colbase + 3) < WW) ? 1.f : 0.f;
    }

    // ---- load vector field into smem, deinterleave (zero out-of-image) ----
    for (int k = tid; k < EXT * EXT / 2; k += NT) {
        int er = k >> 6;              // 64 px-pairs per 128-col row
        int ec = (k & 63) << 1;
        int gr = gi0 + er;
        int gc = gj0 + ec;
        if (INTERIOR) {
            float4 v = *reinterpret_cast<const float4*>(vf + ((size_t)gr * WW + gc) * 2);
            sv0[er * EXT + ec]     = v.x;  sv1[er * EXT + ec]     = v.y;
            sv0[er * EXT + ec + 1] = v.z;  sv1[er * EXT + ec + 1] = v.w;
        } else {
            int grc = min(max(gr, 0), HH - 1);
            int gcc = min(max(gc, 0), WW - 2);
            float4 v = *reinterpret_cast<const float4*>(vf + ((size_t)grc * WW + gcc) * 2);
            float mr = ((unsigned)gr < HH) ? 1.f : 0.f;
            float m0 = mr * (((unsigned)gc < WW) ? 1.f : 0.f);
            float m1 = mr * (((unsigned)(gc + 1) < WW) ? 1.f : 0.f);
            sv0[er * EXT + ec]     = v.x * m0;  sv1[er * EXT + ec]     = v.y * m0;
            sv0[er * EXT + ec + 1] = v.z * m1;  sv1[er * EXT + ec + 1] = v.w * m1;
        }
    }

    // ---- init: u = 0.5*tanh(o)+0.5 (masked on boundary), q = 0 (packed regs) ----
    ull u01[RPW], u23[RPW], q01[RPW], q23[RPW];
#pragma unroll
    for (int r = 0; r < RPW; r++) {
        int er = er0 + r;
        int gr = gi0 + er;
        int grc = INTERIOR ? gr : min(max(gr, 0), HH - 1);
        float4 o4 = *reinterpret_cast<const float4*>(ob + (size_t)grc * WW + cb);
        float t0 = tanh_fast(o4.x), t1 = tanh_fast(o4.y);
        float t2 = tanh_fast(o4.z), t3 = tanh_fast(o4.w);
        if (INTERIOR) {
            u01[r] = fma2(pk2(t0, t1), HF, HF);
            u23[r] = fma2(pk2(t2, t3), HF, HF);
        } else {
            float rm = ((unsigned)gr < HH) ? 1.f : 0.f;
            u01[r] = pk2((cmx * rm) * fmaf(t0, 0.5f, 0.5f), (cmy * rm) * fmaf(t1, 0.5f, 0.5f));
            u23[r] = pk2((cmz * rm) * fmaf(t2, 0.5f, 0.5f), (cmw * rm) * fmaf(t3, 0.5f, 0.5f));
        }
        q01[r] = 0ull;
        q23[r] = 0ull;
    }
    *reinterpret_cast<ulonglong2*>(&xu[w * EXT + lane * 4]) = make_ulonglong2(u01[0], u23[0]);
    __syncthreads();

#pragma unroll 1
    for (int it = 0; it < NITER; it++) {
        const bool last = (it == NITER - 1);

        // ===== fused sweep: per row r: q_new[r]; then (r>=1) u_new[r] =====
        {
            ull v1p01, v1p23;   // v1 of row r-1
#pragma unroll
            for (int r = 0; r < RPW; r++) {
                int er = er0 + r;
                ulonglong2 V0 = *reinterpret_cast<ulonglong2*>(&sv0[er * EXT + lane * 4]);
                ulonglong2 V1 = *reinterpret_cast<ulonglong2*>(&sv1[er * EXT + lane * 4]);

                // ---- q-update row r (prev-iter u) ----
                ull d01, d23;
                if (r < RPW - 1)        { d01 = u01[r + 1]; d23 = u23[r + 1]; }
                else if (w < NWARP - 1) {
                    ulonglong2 t = *reinterpret_cast<ulonglong2*>(&xu[(w + 1) * EXT + lane * 4]);
                    d01 = t.x; d23 = t.y;
                }
                else                    { d01 = 0ull; d23 = 0ull; }
                float ux, uy, uz, uw;
                upk2(u01[r], ux, uy);
                upk2(u23[r], uz, uw);
                float ur = __shfl_down_sync(0xffffffffu, ux, 1);
                if (lane == 31) ur = 0.f;
                ull s01 = pk2(uy, uz);
                ull s23 = pk2(uw, ur);
                ull ddn01 = fma2(u01[r], M1, d01);      // u_dn - u
                ull ddn23 = fma2(u23[r], M1, d23);
                ull drt01 = fma2(u01[r], M1, s01);      // u_rt - u
                ull drt23 = fma2(u23[r], M1, s23);
                ull t01 = mul2(ddn01, V1.x);
                t01 = fma2(drt01, V0.x, t01);
                ull t23 = mul2(ddn23, V1.y);
                t23 = fma2(drt23, V0.y, t23);
                ull qn01 = fma2(t01, MH, q01[r]);       // q - 0.5 t
                ull qn23 = fma2(t23, MH, q23[r]);
                float a0, a1, a2, a3;
                upk2(qn01, a0, a1);
                upk2(qn23, a2, a3);
                q01[r] = pk2(fmaxf(a0, 0.f), fmaxf(a1, 0.f));
                q23[r] = pk2(fmaxf(a2, 0.f), fmaxf(a3, 0.f));

                // ---- u-update row r (r>=1): x = o - v1*q + v1p*qprev - v0*q + p_left ----
                if (r >= 1) {
                    int gr = gi0 + er;
                    int grc = INTERIOR ? gr : min(max(gr, 0), HH - 1);
                    ull nq01 = mul2(q01[r], M1);
                    ull nq23 = mul2(q23[r], M1);
                    ull p01 = mul2(V0.x, q01[r]);
                    ull p23 = mul2(V0.y, q23[r]);
                    float px, py, pz, pw;
                    upk2(p01, px, py);
                    upk2(p23, pz, pw);
                    float pl = __shfl_up_sync(0xffffffffu, pw, 1);
                    if (lane == 0) pl = 0.f;
                    ull ps01 = pk2(pl, px);
                    ull ps23 = pk2(py, pz);
                    ulonglong2 O = *reinterpret_cast<const ulonglong2*>(ob + (size_t)grc * WW + cb);
                    ull x01 = fma2(V1.x, nq01, O.x);
                    x01 = fma2(v1p01, q01[r - 1], x01);
                    x01 = fma2(V0.x, nq01, x01);
                    x01 = add2(x01, ps01);
                    ull x23 = fma2(V1.y, nq23, O.y);
                    x23 = fma2(v1p23, q23[r - 1], x23);
                    x23 = fma2(V0.y, nq23, x23);
                    x23 = add2(x23, ps23);

                    float x0, x1, x2, x3;
                    upk2(x01, x0, x1);
                    upk2(x23, x2, x3);
                    if (!last) {
                        float t0 = tanh_fast(x0), t1 = tanh_fast(x1);
                        float t2 = tanh_fast(x2), t3 = tanh_fast(x3);
                        if (INTERIOR) {
                            u01[r] = fma2(pk2(t0, t1), HF, HF);
                            u23[r] = fma2(pk2(t2, t3), HF, HF);
                        } else {
                            float rm = ((unsigned)gr < HH) ? 1.f : 0.f;
                            u01[r] = pk2((cmx * rm) * fmaf(t0, 0.5f, 0.5f),
                                         (cmy * rm) * fmaf(t1, 0.5f, 0.5f));
                            u23[r] = pk2((cmz * rm) * fmaf(t2, 0.5f, 0.5f),
                                         (cmw * rm) * fmaf(t3, 0.5f, 0.5f));
                        }
                    } else {
                        bool ok = (er >= HALO && er < HALO + TILE &&
                                   lane >= HALO / 4 && lane < (HALO + TILE) / 4);
                        if (!INTERIOR) ok = ok && gr < HH && colbase < WW;
                        if (ok) {
                            *reinterpret_cast<float4*>(out + (size_t)((b * HH + gr) * WW + colbase)) =
                                make_float4(2.f * x0, 2.f * x1, 2.f * x2, 2.f * x3);
                        }
                    }
                }
                v1p01 = V1.x;
                v1p23 = V1.y;
            }
        }
        *reinterpret_cast<ulonglong2*>(&xq[w * EXT + lane * 4]) = make_ulonglong2(q01[RPW - 1], q23[RPW - 1]);
        __syncthreads();

        // ===== epilogue: u-update row 0 (needs q[7] of warp above) =====
        {
            int er = er0;
            int gr = gi0 + er;
            int grc = INTERIOR ? gr : min(max(gr, 0), HH - 1);
            ull qp01, qp23, v1p01, v1p23;
            if (w > 0) {
                ulonglong2 t = *reinterpret_cast<ulonglong2*>(&xq[(w - 1) * EXT + lane * 4]);
                qp01 = t.x; qp23 = t.y;
                ulonglong2 v = *reinterpret_cast<ulonglong2*>(&sv1[(er0 - 1) * EXT + lane * 4]);
                v1p01 = v.x; v1p23 = v.y;
            } else {
                qp01 = 0ull; qp23 = 0ull; v1p01 = 0ull; v1p23 = 0ull;
            }
            ulonglong2 V0 = *reinterpret_cast<ulonglong2*>(&sv0[er * EXT + lane * 4]);
            ulonglong2 V1 = *reinterpret_cast<ulonglong2*>(&sv1[er * EXT + lane * 4]);
            ull nq01 = mul2(q01[0], M1);
            ull nq23 = mul2(q23[0], M1);
            ull p01 = mul2(V0.x, q01[0]);
            ull p23 = mul2(V0.y, q23[0]);
            float px, py, pz, pw;
            upk2(p01, px, py);
            upk2(p23, pz, pw);
            float pl = __shfl_up_sync(0xffffffffu, pw, 1);
            if (lane == 0) pl = 0.f;
            ull ps01 = pk2(pl, px);
            ull ps23 = pk2(py, pz);
            ulonglong2 O = *reinterpret_cast<const ulonglong2*>(ob + (size_t)grc * WW + cb);
            ull x01 = fma2(V1.x, nq01, O.x);
            x01 = fma2(v1p01, qp01, x01);
            x01 = fma2(V0.x, nq01, x01);
            x01 = add2(x01, ps01);
            ull x23 = fma2(V1.y, nq23, O.y);
            x23 = fma2(v1p23, qp23, x23);
            x23 = fma2(V0.y, nq23, x23);
            x23 = add2(x23, ps23);

            float x0, x1, x2, x3;
            upk2(x01, x0, x1);
            upk2(x23, x2, x3);
            if (!last) {
                float t0 = tanh_fast(x0), t1 = tanh_fast(x1);
                float t2 = tanh_fast(x2), t3 = tanh_fast(x3);
                if (INTERIOR) {
                    u01[0] = fma2(pk2(t0, t1), HF, HF);
                    u23[0] = fma2(pk2(t2, t3), HF, HF);
                } else {
                    float rm = ((unsigned)gr < HH) ? 1.f : 0.f;
                    u01[0] = pk2((cmx * rm) * fmaf(t0, 0.5f, 0.5f),
                                 (cmy * rm) * fmaf(t1, 0.5f, 0.5f));
                    u23[0] = pk2((cmz * rm) * fmaf(t2, 0.5f, 0.5f),
                                 (cmw * rm) * fmaf(t3, 0.5f, 0.5f));
                }
                *reinterpret_cast<ulonglong2*>(&xu[w * EXT + lane * 4]) = make_ulonglong2(u01[0], u23[0]);
            } else {
                bool ok = (er >= HALO && er < HALO + TILE &&
                           lane >= HALO / 4 && lane < (HALO + TILE) / 4);
                if (!INTERIOR) ok = ok && gr < HH && colbase < WW;
                if (ok) {
                    *reinterpret_cast<float4*>(out + (size_t)((b * HH + gr) * WW + colbase)) =
                        make_float4(2.f * x0, 2.f * x1, 2.f * x2, 2.f * x3);
                }
            }
        }
        if (!last) __syncthreads();
    }
}

__global__ void __launch_bounds__(NT, 1)
ccs_fused(const float* __restrict__ o, const float* __restrict__ vf,
          float* __restrict__ out) {
    extern __shared__ float sm[];
    const int tx = blockIdx.x, ty = blockIdx.y, b = blockIdx.z;
    // interior tile: its EXT window never leaves the image
    const bool interior = (tx >= 1) && (tx <= 8) && (ty >= 1) && (ty <= 8);
    if (interior) run_tile<true >(o, vf, out, sm, tx, ty, b);
    else          run_tile<false>(o, vf, out, sm, tx, ty, b);
}

extern "C" void kernel_launch(void* const* d_in, const int* in_sizes, int n_in,
                              void* d_out, int out_size) {
    const float* o  = (const float*)d_in[0];
    const float* vf = (const float*)d_in[1];
    float* out = (float*)d_out;

    static bool attr_set = false;
    if (!attr_set) {
        cudaFuncSetAttribute(ccs_fused, cudaFuncAttributeMaxDynamicSharedMemorySize,
                             SMEM_BYTES);
        attr_set = true;
    }

    dim3 grid((WW + TILE - 1) / TILE, (HH + TILE - 1) / TILE, BATCH);  // 10 x 10 x 8
    ccs_fused<<<grid, NT, SMEM_BYTES>>>(o, vf, out);
}